// round 1
// baseline (speedup 1.0000x reference)
#include <cuda_runtime.h>
#include <cuda_bf16.h>
#include <cstdint>

#define B_  4
#define V_  778
#define F_  1538
#define NT  3076          // 2*F_ (faces + reversed faces)
#define RW  256
#define FARV 10.0f
#define TC  256           // triangle chunk per raster block

// ---------------- scratch (static device globals; no allocation) -------------
__device__ float  g_uvz [B_ * V_ * 3];
__device__ float4 g_coef[B_ * NT * 3];   // per tri: (U0,V0,W0,U1) (V1,W1,Gx,Gy) (Gc,-,-,-)
__device__ float4 g_bbox[B_ * NT];       // (xmin, xmax, ymin, ymax)
__device__ unsigned g_mx[B_];            // max foreground depth (bit-punned float)
__device__ unsigned g_mn[B_];            // min depth incl FAR

// ---------------- K0: reset reduction buffers (graph-replay safe) ------------
__global__ void k_init() {
    int t = threadIdx.x;
    if (t < B_) { g_mx[t] = 0u; g_mn[t] = __float_as_uint(FARV); }
}

// ---------------- K1: project vertices ---------------------------------------
__global__ void k_project(const float* __restrict__ verts,
                          const float* __restrict__ intr,
                          const float* __restrict__ R,
                          const float* __restrict__ t,
                          const float* __restrict__ dist) {
    int idx = blockIdx.x * blockDim.x + threadIdx.x;
    if (idx >= B_ * V_) return;
    int b = idx / V_;
    const float* p  = verts + idx * 3;
    const float* Rb = R    + b * 9;
    const float* tb = t    + b * 3;
    const float* Kb = intr + b * 9;
    const float* db = dist + b * 5;

    float px = p[0], py = p[1], pz = p[2];
    float x = Rb[0]*px + Rb[1]*py + Rb[2]*pz + tb[0];
    float y = Rb[3]*px + Rb[4]*py + Rb[5]*pz + tb[1];
    float z = Rb[6]*px + Rb[7]*py + Rb[8]*pz + tb[2];

    float zi = z + 1e-9f;
    float x_ = x / zi, y_ = y / zi;
    float k1 = db[0], k2 = db[1], p1 = db[2], p2 = db[3], k3 = db[4];
    float r2 = x_*x_ + y_*y_;
    float radial = 1.0f + k1*r2 + k2*r2*r2 + k3*r2*r2*r2;
    float x2 = x_*radial + 2.0f*p1*x_*y_ + p2*(r2 + 2.0f*x_*x_);
    float y2 = y_*radial + p1*(r2 + 2.0f*y_*y_) + 2.0f*p2*x_*y_;
    float u  = Kb[0]*x2 + Kb[1]*y2 + Kb[2];
    float vv = Kb[3]*x2 + Kb[4]*y2 + Kb[5];
    vv = 256.0f - vv;
    u  = 2.0f * (u  - 128.0f) / 256.0f;
    vv = 2.0f * (vv - 128.0f) / 256.0f;

    g_uvz[idx*3 + 0] = u;
    g_uvz[idx*3 + 1] = vv;
    g_uvz[idx*3 + 2] = z;
}

// ---------------- K2: triangle setup -----------------------------------------
__global__ void k_setup(const int* __restrict__ faces) {
    int idx = blockIdx.x * blockDim.x + threadIdx.x;
    if (idx >= B_ * NT) return;
    int b  = idx / NT;
    int tt = idx - b * NT;

    int base = (b * F_ + (tt < F_ ? tt : tt - F_)) * 3;
    int i0 = faces[base + 0], i1 = faces[base + 1], i2 = faces[base + 2];
    if (tt >= F_) { int tmp = i0; i0 = i2; i2 = tmp; }  // reversed copy

    const float* va = g_uvz + (b * V_ + i0) * 3;
    const float* vb = g_uvz + (b * V_ + i1) * 3;
    const float* vc = g_uvz + (b * V_ + i2) * 3;
    float ax = va[0], ay = va[1], az = va[2];
    float bx = vb[0], by = vb[1], bz = vb[2];
    float cx = vc[0], cy = vc[1], cz = vc[2];

    float den = (bx - ax) * (cy - ay) - (by - ay) * (cx - ax);
    bool ok = (fabsf(den) > 1e-8f) && (az > 1e-8f) && (bz > 1e-8f) && (cz > 1e-8f);

    float4 c0, c1, c2, bb;
    if (!ok) {
        c0 = make_float4(0.f, 0.f, -1e30f, 0.f);
        c1 = make_float4(0.f, 0.f, 0.f, 0.f);
        c2 = make_float4(0.f, 0.f, 0.f, 0.f);
        bb = make_float4(2e30f, -2e30f, 2e30f, -2e30f);   // never overlaps any tile
    } else {
        float id = 1.0f / den;
        float U0 = (by - cy) * id, V0 = (cx - bx) * id;
        float W0 = -(U0 * cx + V0 * cy);
        float U1 = (cy - ay) * id, V1 = (ax - cx) * id;
        float W1 = -(U1 * cx + V1 * cy);
        float ra = 1.0f / az, rb = 1.0f / bz, rc = 1.0f / cz;
        float dA = ra - rc, dB = rb - rc;
        float Gx = U0 * dA + U1 * dB;
        float Gy = V0 * dA + V1 * dB;
        float Gc = rc + W0 * dA + W1 * dB;
        c0 = make_float4(U0, V0, W0, U1);
        c1 = make_float4(V1, W1, Gx, Gy);
        c2 = make_float4(Gc, 0.f, 0.f, 0.f);
        bb = make_float4(fminf(ax, fminf(bx, cx)), fmaxf(ax, fmaxf(bx, cx)),
                         fminf(ay, fminf(by, cy)), fmaxf(ay, fmaxf(by, cy)));
    }
    g_coef[idx * 3 + 0] = c0;
    g_coef[idx * 3 + 1] = c1;
    g_coef[idx * 3 + 2] = c2;
    g_bbox[idx]         = bb;
}

// ---------------- K3: tiled rasterizer ---------------------------------------
__global__ void __launch_bounds__(256) k_raster(float* __restrict__ dep,
                                                float* __restrict__ mask) {
    __shared__ float4 sc0[TC], sc1[TC];
    __shared__ float  sc2[TC];
    __shared__ int    scnt;
    __shared__ float  smx[256], smn[256];

    int b   = blockIdx.z;
    int tid = threadIdx.x;
    int ix  = blockIdx.x * 16 + (tid & 15);
    int iy  = blockIdx.y * 16 + (tid >> 4);

    float x = 2.0f * (ix + 0.5f) / 256.0f - 1.0f;
    float y = 2.0f * (iy + 0.5f) / 256.0f - 1.0f;

    float xlo = 2.0f * (blockIdx.x * 16 +  0.5f) / 256.0f - 1.0f;
    float xhi = 2.0f * (blockIdx.x * 16 + 15.5f) / 256.0f - 1.0f;
    float ylo = 2.0f * (blockIdx.y * 16 +  0.5f) / 256.0f - 1.0f;
    float yhi = 2.0f * (blockIdx.y * 16 + 15.5f) / 256.0f - 1.0f;

    const float4* bbox = g_bbox + b * NT;
    const float4* coef = g_coef + (size_t)b * NT * 3;

    float maxinv = 0.0f;

    for (int basei = 0; basei < NT; basei += TC) {
        if (tid == 0) scnt = 0;
        __syncthreads();
        int tI = basei + tid;
        if (tI < NT) {
            float4 bb = bbox[tI];
            if (bb.x <= xhi && bb.y >= xlo && bb.z <= yhi && bb.w >= ylo) {
                int s = atomicAdd(&scnt, 1);
                sc0[s] = coef[tI * 3 + 0];
                sc1[s] = coef[tI * 3 + 1];
                sc2[s] = coef[tI * 3 + 2].x;
            }
        }
        __syncthreads();
        int n = scnt;
        #pragma unroll 4
        for (int j = 0; j < n; j++) {
            float4 a = sc0[j];
            float4 c = sc1[j];
            float gc = sc2[j];
            float w0  = fmaf(a.x, x, fmaf(a.y, y, a.z));
            float w1  = fmaf(a.w, x, fmaf(c.x, y, c.y));
            float w2  = 1.0f - w0 - w1;
            float inv = fmaf(c.z, x, fmaf(c.w, y, gc));
            float m   = fminf(fminf(w0, w1), w2);
            if (m >= 0.0f && inv > 1e-8f) maxinv = fmaxf(maxinv, inv);
        }
        __syncthreads();
    }

    bool  cov = maxinv > 0.0f;
    float z   = FARV;
    if (cov) z = fminf(FARV, 1.0f / maxinv);

    int pix = b * (RW * RW) + iy * RW + ix;
    dep [pix] = z;
    mask[pix] = cov ? 1.0f : 0.0f;

    smx[tid] = (cov && z < FARV) ? z : 0.0f;
    smn[tid] = z;
    __syncthreads();
    for (int s = 128; s > 0; s >>= 1) {
        if (tid < s) {
            smx[tid] = fmaxf(smx[tid], smx[tid + s]);
            smn[tid] = fminf(smn[tid], smn[tid + s]);
        }
        __syncthreads();
    }
    if (tid == 0) {
        atomicMax(&g_mx[b], __float_as_uint(smx[0]));
        atomicMin(&g_mn[b], __float_as_uint(smn[0]));
    }
}

// ---------------- K4: depth normalization (in place over dep) ----------------
__global__ void k_finalize(float* __restrict__ dep) {
    int idx = blockIdx.x * blockDim.x + threadIdx.x;
    if (idx >= B_ * RW * RW) return;
    int b = idx >> 16;
    float mx = __uint_as_float(g_mx[b]);
    float mn = __uint_as_float(g_mn[b]);
    float z  = dep[idx];
    float nd = (mx - z) / (mx - mn + 1e-4f);
    dep[idx] = fminf(fmaxf(nd, 0.0f), 1.0f);
}

// ---------------- launch ------------------------------------------------------
extern "C" void kernel_launch(void* const* d_in, const int* in_sizes, int n_in,
                              void* d_out, int out_size) {
    const float* vertices = (const float*)d_in[0];
    const int*   faces    = (const int*)  d_in[1];
    const float* intr     = (const float*)d_in[2];
    const float* R        = (const float*)d_in[3];
    const float* t        = (const float*)d_in[4];
    const float* dist     = (const float*)d_in[5];

    float* out  = (float*)d_out;
    float* dep  = out;
    float* mask = out + B_ * RW * RW;

    k_init<<<1, 32>>>();
    k_project<<<(B_ * V_ + 255) / 256, 256>>>(vertices, intr, R, t, dist);
    k_setup<<<(B_ * NT + 255) / 256, 256>>>(faces);
    dim3 grid(RW / 16, RW / 16, B_);
    k_raster<<<grid, 256>>>(dep, mask);
    k_finalize<<<(B_ * RW * RW + 255) / 256, 256>>>(dep);
}

// round 2
// speedup vs baseline: 2.2060x; 2.2060x over previous
#include <cuda_runtime.h>
#include <cuda_bf16.h>
#include <cstdint>

#define B_   4
#define V_   778
#define F_   1538
#define NT   3076          // 2*F_ (faces + reversed)
#define RW   256
#define NPIX (RW * RW)
#define FARV 10.0f
#define TILE 32
#define TC   256           // triangles classified per chunk
#define S_   4             // triangle slices per batch
#define SLICE ((NT + S_ - 1) / S_)

// ---------------- scratch (static device globals; no allocation) -------------
__device__ float    g_uvz [B_ * V_ * 3];
__device__ float4   g_coef[B_ * NT * 3];   // (U0,V0,W0,U1) (V1,W1,Gx,Gy) (Gc,-,-,-)
__device__ float4   g_bbox[B_ * NT];       // (xmin, xmax, ymin, ymax)
__device__ unsigned g_inv [B_ * NPIX];     // per-pixel max(inv) as ordered uint
__device__ unsigned g_mx  [B_];
__device__ unsigned g_mn  [B_];

// ---------------- K0: clear scratch (graph-replay safe) ----------------------
__global__ void k_init() {
    int i = blockIdx.x * blockDim.x + threadIdx.x;
    for (; i < B_ * NPIX; i += gridDim.x * blockDim.x) g_inv[i] = 0u;
    if (blockIdx.x == 0 && threadIdx.x < B_) {
        g_mx[threadIdx.x] = 0u;
        g_mn[threadIdx.x] = __float_as_uint(FARV);
    }
}

// ---------------- K1: project vertices ---------------------------------------
__global__ void k_project(const float* __restrict__ verts,
                          const float* __restrict__ intr,
                          const float* __restrict__ R,
                          const float* __restrict__ t,
                          const float* __restrict__ dist) {
    int idx = blockIdx.x * blockDim.x + threadIdx.x;
    if (idx >= B_ * V_) return;
    int b = idx / V_;
    const float* p  = verts + idx * 3;
    const float* Rb = R    + b * 9;
    const float* tb = t    + b * 3;
    const float* Kb = intr + b * 9;
    const float* db = dist + b * 5;

    float px = p[0], py = p[1], pz = p[2];
    float x = Rb[0]*px + Rb[1]*py + Rb[2]*pz + tb[0];
    float y = Rb[3]*px + Rb[4]*py + Rb[5]*pz + tb[1];
    float z = Rb[6]*px + Rb[7]*py + Rb[8]*pz + tb[2];

    float zi = z + 1e-9f;
    float x_ = x / zi, y_ = y / zi;
    float k1 = db[0], k2 = db[1], p1 = db[2], p2 = db[3], k3 = db[4];
    float r2 = x_*x_ + y_*y_;
    float radial = 1.0f + k1*r2 + k2*r2*r2 + k3*r2*r2*r2;
    float x2 = x_*radial + 2.0f*p1*x_*y_ + p2*(r2 + 2.0f*x_*x_);
    float y2 = y_*radial + p1*(r2 + 2.0f*y_*y_) + 2.0f*p2*x_*y_;
    float u  = Kb[0]*x2 + Kb[1]*y2 + Kb[2];
    float vv = Kb[3]*x2 + Kb[4]*y2 + Kb[5];
    vv = 256.0f - vv;
    u  = 2.0f * (u  - 128.0f) / 256.0f;
    vv = 2.0f * (vv - 128.0f) / 256.0f;

    g_uvz[idx*3 + 0] = u;
    g_uvz[idx*3 + 1] = vv;
    g_uvz[idx*3 + 2] = z;
}

// ---------------- K2: triangle setup -----------------------------------------
__global__ void k_setup(const int* __restrict__ faces) {
    int idx = blockIdx.x * blockDim.x + threadIdx.x;
    if (idx >= B_ * NT) return;
    int b  = idx / NT;
    int tt = idx - b * NT;

    int base = (b * F_ + (tt < F_ ? tt : tt - F_)) * 3;
    int i0 = faces[base + 0], i1 = faces[base + 1], i2 = faces[base + 2];
    if (tt >= F_) { int tmp = i0; i0 = i2; i2 = tmp; }

    const float* va = g_uvz + (b * V_ + i0) * 3;
    const float* vb = g_uvz + (b * V_ + i1) * 3;
    const float* vc = g_uvz + (b * V_ + i2) * 3;
    float ax = va[0], ay = va[1], az = va[2];
    float bx = vb[0], by = vb[1], bz = vb[2];
    float cx = vc[0], cy = vc[1], cz = vc[2];

    float den = (bx - ax) * (cy - ay) - (by - ay) * (cx - ax);
    bool ok = (fabsf(den) > 1e-8f) && (az > 1e-8f) && (bz > 1e-8f) && (cz > 1e-8f);

    float4 c0, c1, c2, bb;
    if (!ok) {
        c0 = make_float4(0.f, 0.f, -1e30f, 0.f);
        c1 = make_float4(0.f, 0.f, 0.f, 0.f);
        c2 = make_float4(0.f, 0.f, 0.f, 0.f);
        bb = make_float4(2e30f, -2e30f, 2e30f, -2e30f);
    } else {
        float id = 1.0f / den;
        float U0 = (by - cy) * id, V0 = (cx - bx) * id;
        float W0 = -(U0 * cx + V0 * cy);
        float U1 = (cy - ay) * id, V1 = (ax - cx) * id;
        float W1 = -(U1 * cx + V1 * cy);
        float ra = 1.0f / az, rb = 1.0f / bz, rc = 1.0f / cz;
        float dA = ra - rc, dB = rb - rc;
        float Gx = U0 * dA + U1 * dB;
        float Gy = V0 * dA + V1 * dB;
        float Gc = rc + W0 * dA + W1 * dB;
        c0 = make_float4(U0, V0, W0, U1);
        c1 = make_float4(V1, W1, Gx, Gy);
        c2 = make_float4(Gc, 0.f, 0.f, 0.f);
        bb = make_float4(fminf(ax, fminf(bx, cx)), fmaxf(ax, fmaxf(bx, cx)),
                         fminf(ay, fminf(by, cy)), fmaxf(ay, fmaxf(by, cy)));
    }
    g_coef[idx * 3 + 0] = c0;
    g_coef[idx * 3 + 1] = c1;
    g_coef[idx * 3 + 2] = c2;
    g_bbox[idx]         = bb;
}

// affine corner bounds over [xlo,xhi]x[ylo,yhi]
__device__ __forceinline__ float aff_max(float U, float V, float W,
                                         float xlo, float xhi, float ylo, float yhi) {
    return fmaf(U, U > 0.f ? xhi : xlo, fmaf(V, V > 0.f ? yhi : ylo, W));
}
__device__ __forceinline__ float aff_min(float U, float V, float W,
                                         float xlo, float xhi, float ylo, float yhi) {
    return fmaf(U, U > 0.f ? xlo : xhi, fmaf(V, V > 0.f ? ylo : yhi, W));
}

// ---------------- K3: classified tiled rasterizer ----------------------------
// tile 32x32 px, 256 threads, 4 consecutive px per thread, triangles sliced on z
__global__ void __launch_bounds__(256) k_raster() {
    __shared__ float4 spA[TC], spB[TC];
    __shared__ float  spC[TC];
    __shared__ float4 sfl[TC];
    __shared__ int    nP, nF;

    int bz = blockIdx.z;
    int b  = bz & (B_ - 1);
    int sl = bz >> 2;                // slice id (S_=4)
    int t0 = sl * SLICE;
    int t1 = min(NT, t0 + SLICE);

    int tid = threadIdx.x;
    int row = tid >> 3;              // 0..31
    int xg  = tid & 7;               // 0..7
    int tx  = blockIdx.x * TILE;
    int ty  = blockIdx.y * TILE;
    int ix0 = tx + xg * 4;
    int iy  = ty + row;

    float y  = 2.0f * (iy + 0.5f) / 256.0f - 1.0f;
    float x0 = 2.0f * (ix0 + 0.5f) / 256.0f - 1.0f;
    float x1 = 2.0f * (ix0 + 1.5f) / 256.0f - 1.0f;
    float x2 = 2.0f * (ix0 + 2.5f) / 256.0f - 1.0f;
    float x3 = 2.0f * (ix0 + 3.5f) / 256.0f - 1.0f;

    float xlo = 2.0f * (tx +  0.5f) / 256.0f - 1.0f;
    float xhi = 2.0f * (tx + 31.5f) / 256.0f - 1.0f;
    float ylo = 2.0f * (ty +  0.5f) / 256.0f - 1.0f;
    float yhi = 2.0f * (ty + 31.5f) / 256.0f - 1.0f;

    const float4* bbox = g_bbox + b * NT;
    const float4* coef = g_coef + (size_t)b * NT * 3;

    float m0 = 0.f, m1 = 0.f, m2 = 0.f, m3 = 0.f;

    for (int basei = t0; basei < t1; basei += TC) {
        if (tid == 0) { nP = 0; nF = 0; }
        __syncthreads();
        int tI = basei + tid;
        if (tI < t1) {
            float4 bb = bbox[tI];
            if (bb.x <= xhi && bb.y >= xlo && bb.z <= yhi && bb.w >= ylo) {
                float4 a = coef[tI * 3 + 0];
                float4 c = coef[tI * 3 + 1];
                float gc = coef[tI * 3 + 2].x;
                float U2 = -(a.x + a.w), V2 = -(a.y + c.x), W2 = 1.0f - a.z - c.y;

                float mx0 = aff_max(a.x, a.y, a.z, xlo, xhi, ylo, yhi);
                float mx1 = aff_max(a.w, c.x, c.y, xlo, xhi, ylo, yhi);
                float mx2 = aff_max(U2,  V2,  W2,  xlo, xhi, ylo, yhi);
                float imx = aff_max(c.z, c.w, gc,  xlo, xhi, ylo, yhi);

                bool rej = (mx0 < -1e-6f) || (mx1 < -1e-6f) || (mx2 < -1e-6f) ||
                           (imx <= 1e-8f);
                if (!rej) {
                    float mn0 = aff_min(a.x, a.y, a.z, xlo, xhi, ylo, yhi);
                    float mn1 = aff_min(a.w, c.x, c.y, xlo, xhi, ylo, yhi);
                    float mn2 = aff_min(U2,  V2,  W2,  xlo, xhi, ylo, yhi);
                    float imn = aff_min(c.z, c.w, gc,  xlo, xhi, ylo, yhi);
                    bool full = (mn0 > 1e-6f) && (mn1 > 1e-6f) && (mn2 > 1e-6f) &&
                                (imn > 1e-6f);
                    if (full) {
                        int s = atomicAdd(&nF, 1);
                        sfl[s] = make_float4(c.z, c.w, gc, 0.f);
                    } else {
                        int s = atomicAdd(&nP, 1);
                        spA[s] = a; spB[s] = c; spC[s] = gc;
                    }
                }
            }
        }
        __syncthreads();
        int np = nP, nf = nF;

        // partial: full per-pixel test (same fma nesting as reference path)
        for (int j = 0; j < np; j++) {
            float4 a = spA[j];
            float4 c = spB[j];
            float gc = spC[j];
            float ty0 = fmaf(a.y, y, a.z);
            float ty1 = fmaf(c.x, y, c.y);
            float tyi = fmaf(c.w, y, gc);
            {
                float w0 = fmaf(a.x, x0, ty0), w1 = fmaf(a.w, x0, ty1);
                float w2 = 1.0f - w0 - w1;
                float iv = fmaf(c.z, x0, tyi);
                if (fminf(fminf(w0, w1), w2) >= 0.f) m0 = fmaxf(m0, iv);
            }
            {
                float w0 = fmaf(a.x, x1, ty0), w1 = fmaf(a.w, x1, ty1);
                float w2 = 1.0f - w0 - w1;
                float iv = fmaf(c.z, x1, tyi);
                if (fminf(fminf(w0, w1), w2) >= 0.f) m1 = fmaxf(m1, iv);
            }
            {
                float w0 = fmaf(a.x, x2, ty0), w1 = fmaf(a.w, x2, ty1);
                float w2 = 1.0f - w0 - w1;
                float iv = fmaf(c.z, x2, tyi);
                if (fminf(fminf(w0, w1), w2) >= 0.f) m2 = fmaxf(m2, iv);
            }
            {
                float w0 = fmaf(a.x, x3, ty0), w1 = fmaf(a.w, x3, ty1);
                float w2 = 1.0f - w0 - w1;
                float iv = fmaf(c.z, x3, tyi);
                if (fminf(fminf(w0, w1), w2) >= 0.f) m3 = fmaxf(m3, iv);
            }
        }

        // full-accept: every pixel valid -> just interpolate inv and fmax
        #pragma unroll 2
        for (int j = 0; j < nf; j++) {
            float4 f = sfl[j];
            float tyi = fmaf(f.y, y, f.z);
            m0 = fmaxf(m0, fmaf(f.x, x0, tyi));
            m1 = fmaxf(m1, fmaf(f.x, x1, tyi));
            m2 = fmaxf(m2, fmaf(f.x, x2, tyi));
            m3 = fmaxf(m3, fmaf(f.x, x3, tyi));
        }
        __syncthreads();
    }

    unsigned* dst = g_inv + b * NPIX + iy * RW + ix0;
    if (m0 > 0.f) atomicMax(dst + 0, __float_as_uint(m0));
    if (m1 > 0.f) atomicMax(dst + 1, __float_as_uint(m1));
    if (m2 > 0.f) atomicMax(dst + 2, __float_as_uint(m2));
    if (m3 > 0.f) atomicMax(dst + 3, __float_as_uint(m3));
}

// ---------------- K4: inv -> z, mask, per-batch min/max ----------------------
__global__ void __launch_bounds__(256) k_zpass(float* __restrict__ dep,
                                               float* __restrict__ mask) {
    __shared__ float smx[256], smn[256];
    int idx = blockIdx.x * 256 + threadIdx.x;
    int b   = idx >> 16;
    int tid = threadIdx.x;

    float mi  = __uint_as_float(g_inv[idx]);
    bool  cov = mi > 0.f;
    float z   = cov ? fminf(FARV, 1.0f / mi) : FARV;

    dep [idx] = z;
    mask[idx] = cov ? 1.0f : 0.0f;

    smx[tid] = (cov && z < FARV) ? z : 0.0f;
    smn[tid] = z;
    __syncthreads();
    for (int s = 128; s > 0; s >>= 1) {
        if (tid < s) {
            smx[tid] = fmaxf(smx[tid], smx[tid + s]);
            smn[tid] = fminf(smn[tid], smn[tid + s]);
        }
        __syncthreads();
    }
    if (tid == 0) {
        atomicMax(&g_mx[b], __float_as_uint(smx[0]));
        atomicMin(&g_mn[b], __float_as_uint(smn[0]));
    }
}

// ---------------- K5: depth normalization ------------------------------------
__global__ void k_finalize(float* __restrict__ dep) {
    int idx = blockIdx.x * blockDim.x + threadIdx.x;
    if (idx >= B_ * NPIX) return;
    int b = idx >> 16;
    float mx = __uint_as_float(g_mx[b]);
    float mn = __uint_as_float(g_mn[b]);
    float z  = dep[idx];
    float nd = (mx - z) / (mx - mn + 1e-4f);
    dep[idx] = fminf(fmaxf(nd, 0.0f), 1.0f);
}

// ---------------- launch ------------------------------------------------------
extern "C" void kernel_launch(void* const* d_in, const int* in_sizes, int n_in,
                              void* d_out, int out_size) {
    const float* vertices = (const float*)d_in[0];
    const int*   faces    = (const int*)  d_in[1];
    const float* intr     = (const float*)d_in[2];
    const float* R        = (const float*)d_in[3];
    const float* t        = (const float*)d_in[4];
    const float* dist     = (const float*)d_in[5];

    float* out  = (float*)d_out;
    float* dep  = out;
    float* mask = out + B_ * NPIX;

    k_init<<<256, 256>>>();
    k_project<<<(B_ * V_ + 255) / 256, 256>>>(vertices, intr, R, t, dist);
    k_setup<<<(B_ * NT + 255) / 256, 256>>>(faces);
    dim3 grid(RW / TILE, RW / TILE, B_ * S_);
    k_raster<<<grid, 256>>>();
    k_zpass<<<B_ * NPIX / 256, 256>>>(dep, mask);
    k_finalize<<<(B_ * NPIX + 255) / 256, 256>>>(dep);
}

// round 3
// speedup vs baseline: 2.4870x; 1.1274x over previous
#include <cuda_runtime.h>
#include <cuda_bf16.h>
#include <cstdint>

#define B_   4
#define V_   778
#define F_   1538
#define NT   3076          // 2*F_ (faces + reversed)
#define RW   256
#define NPIX (RW * RW)
#define FARV 10.0f
#define TILE 32
#define TC   256           // triangles classified per chunk
#define S_   8             // triangle slices per batch
#define SLICE ((NT + S_ - 1) / S_)

// ---------------- scratch (static device globals; no allocation) -------------
__device__ float4   g_cA  [B_ * NT];     // U0,V0,W0,U1
__device__ float4   g_cB  [B_ * NT];     // V1,W1,Gx,Gy
__device__ float    g_cC  [B_ * NT];     // Gc
__device__ float4   g_bbox[B_ * NT];     // xmin,xmax,ymin,ymax
__device__ unsigned g_inv [B_ * NPIX];   // per-pixel max(inv) as ordered uint
__device__ unsigned g_mx  [B_];
__device__ unsigned g_mn  [B_];

// ---------------- projection helper (bit-identical per vertex) ---------------
__device__ __forceinline__ float3 proj_vert(const float* __restrict__ verts,
                                            const float* __restrict__ Rb,
                                            const float* __restrict__ tb,
                                            const float* __restrict__ Kb,
                                            const float* __restrict__ db,
                                            int vglob) {
    const float* p = verts + vglob * 3;
    float px = p[0], py = p[1], pz = p[2];
    float x = Rb[0]*px + Rb[1]*py + Rb[2]*pz + tb[0];
    float y = Rb[3]*px + Rb[4]*py + Rb[5]*pz + tb[1];
    float z = Rb[6]*px + Rb[7]*py + Rb[8]*pz + tb[2];

    float zi = z + 1e-9f;
    float x_ = x / zi, y_ = y / zi;
    float k1 = db[0], k2 = db[1], p1 = db[2], p2 = db[3], k3 = db[4];
    float r2 = x_*x_ + y_*y_;
    float radial = 1.0f + k1*r2 + k2*r2*r2 + k3*r2*r2*r2;
    float x2 = x_*radial + 2.0f*p1*x_*y_ + p2*(r2 + 2.0f*x_*x_);
    float y2 = y_*radial + p1*(r2 + 2.0f*y_*y_) + 2.0f*p2*x_*y_;
    float u  = Kb[0]*x2 + Kb[1]*y2 + Kb[2];
    float vv = Kb[3]*x2 + Kb[4]*y2 + Kb[5];
    vv = 256.0f - vv;
    u  = 2.0f * (u  - 128.0f) / 256.0f;
    vv = 2.0f * (vv - 128.0f) / 256.0f;
    return make_float3(u, vv, z);
}

// ---------------- K1: fused setup (project inline) + scratch clear -----------
__global__ void __launch_bounds__(256) k_prep(const float* __restrict__ verts,
                                              const int*   __restrict__ faces,
                                              const float* __restrict__ intr,
                                              const float* __restrict__ R,
                                              const float* __restrict__ t,
                                              const float* __restrict__ dist) {
    int gid = blockIdx.x * 256 + threadIdx.x;

    if (gid < B_ * NT) {
        int b  = gid / NT;
        int tt = gid - b * NT;
        const float* Rb = R    + b * 9;
        const float* tb = t    + b * 3;
        const float* Kb = intr + b * 9;
        const float* db = dist + b * 5;

        int base = (b * F_ + (tt < F_ ? tt : tt - F_)) * 3;
        int i0 = faces[base + 0], i1 = faces[base + 1], i2 = faces[base + 2];
        if (tt >= F_) { int tmp = i0; i0 = i2; i2 = tmp; }

        float3 A = proj_vert(verts, Rb, tb, Kb, db, b * V_ + i0);
        float3 Bv = proj_vert(verts, Rb, tb, Kb, db, b * V_ + i1);
        float3 Cv = proj_vert(verts, Rb, tb, Kb, db, b * V_ + i2);
        float ax = A.x,  ay = A.y,  az = A.z;
        float bx = Bv.x, by = Bv.y, bz = Bv.z;
        float cx = Cv.x, cy = Cv.y, cz = Cv.z;

        float den = (bx - ax) * (cy - ay) - (by - ay) * (cx - ax);
        bool ok = (fabsf(den) > 1e-8f) && (az > 1e-8f) && (bz > 1e-8f) && (cz > 1e-8f);

        float4 cA, cB, bb; float cC;
        if (!ok) {
            cA = make_float4(0.f, 0.f, -1e30f, 0.f);
            cB = make_float4(0.f, 0.f, 0.f, 0.f);
            cC = 0.f;
            bb = make_float4(2e30f, -2e30f, 2e30f, -2e30f);
        } else {
            float id = 1.0f / den;
            float U0 = (by - cy) * id, V0 = (cx - bx) * id;
            float W0 = -(U0 * cx + V0 * cy);
            float U1 = (cy - ay) * id, V1 = (ax - cx) * id;
            float W1 = -(U1 * cx + V1 * cy);
            float ra = 1.0f / az, rb = 1.0f / bz, rc = 1.0f / cz;
            float dA = ra - rc, dB = rb - rc;
            float Gx = U0 * dA + U1 * dB;
            float Gy = V0 * dA + V1 * dB;
            float Gc = rc + W0 * dA + W1 * dB;
            cA = make_float4(U0, V0, W0, U1);
            cB = make_float4(V1, W1, Gx, Gy);
            cC = Gc;
            bb = make_float4(fminf(ax, fminf(bx, cx)), fmaxf(ax, fmaxf(bx, cx)),
                             fminf(ay, fminf(by, cy)), fmaxf(ay, fmaxf(by, cy)));
        }
        g_cA[gid]   = cA;
        g_cB[gid]   = cB;
        g_cC[gid]   = cC;
        g_bbox[gid] = bb;
    }

    if (gid < B_ * NPIX) g_inv[gid] = 0u;
    if (gid < B_) { g_mx[gid] = 0u; g_mn[gid] = __float_as_uint(FARV); }
}

// affine corner bounds over [xlo,xhi]x[ylo,yhi]
__device__ __forceinline__ float aff_max(float U, float V, float W,
                                         float xlo, float xhi, float ylo, float yhi) {
    return fmaf(U, U > 0.f ? xhi : xlo, fmaf(V, V > 0.f ? yhi : ylo, W));
}
__device__ __forceinline__ float aff_min(float U, float V, float W,
                                         float xlo, float xhi, float ylo, float yhi) {
    return fmaf(U, U > 0.f ? xlo : xhi, fmaf(V, V > 0.f ? ylo : yhi, W));
}

// ---------------- K2: classified tiled rasterizer ----------------------------
// tile 32x32 px, 256 threads, 4 consecutive px per thread, triangles sliced on z
__global__ void __launch_bounds__(256) k_raster() {
    __shared__ float4 spA[TC], spB[TC];
    __shared__ float  spC[TC];
    __shared__ float4 sfl[TC];
    __shared__ int    nP, nF;

    int bz = blockIdx.z;
    int b  = bz & (B_ - 1);
    int sl = bz >> 2;                // slice id
    int t0 = sl * SLICE;
    int t1 = min(NT, t0 + SLICE);

    int tid = threadIdx.x;
    int row = tid >> 3;              // 0..31
    int xg  = tid & 7;               // 0..7
    int tx  = blockIdx.x * TILE;
    int ty  = blockIdx.y * TILE;
    int ix0 = tx + xg * 4;
    int iy  = ty + row;

    float y  = 2.0f * (iy + 0.5f) / 256.0f - 1.0f;
    float x0 = 2.0f * (ix0 + 0.5f) / 256.0f - 1.0f;
    float x1 = 2.0f * (ix0 + 1.5f) / 256.0f - 1.0f;
    float x2 = 2.0f * (ix0 + 2.5f) / 256.0f - 1.0f;
    float x3 = 2.0f * (ix0 + 3.5f) / 256.0f - 1.0f;

    float xlo = 2.0f * (tx +  0.5f) / 256.0f - 1.0f;
    float xhi = 2.0f * (tx + 31.5f) / 256.0f - 1.0f;
    float ylo = 2.0f * (ty +  0.5f) / 256.0f - 1.0f;
    float yhi = 2.0f * (ty + 31.5f) / 256.0f - 1.0f;

    const float4* bbox = g_bbox + b * NT;
    const float4* cAp  = g_cA   + b * NT;
    const float4* cBp  = g_cB   + b * NT;
    const float*  cCp  = g_cC   + b * NT;

    float m0 = 0.f, m1 = 0.f, m2 = 0.f, m3 = 0.f;

    for (int basei = t0; basei < t1; basei += TC) {
        if (tid == 0) { nP = 0; nF = 0; }
        __syncthreads();
        int tI = basei + tid;
        if (tI < t1) {
            float4 bb = bbox[tI];
            if (bb.x <= xhi && bb.y >= xlo && bb.z <= yhi && bb.w >= ylo) {
                float4 a = cAp[tI];
                float4 c = cBp[tI];
                float gc = cCp[tI];
                float U2 = -(a.x + a.w), V2 = -(a.y + c.x), W2 = 1.0f - a.z - c.y;

                float mx0 = aff_max(a.x, a.y, a.z, xlo, xhi, ylo, yhi);
                float mx1 = aff_max(a.w, c.x, c.y, xlo, xhi, ylo, yhi);
                float mx2 = aff_max(U2,  V2,  W2,  xlo, xhi, ylo, yhi);
                float imx = aff_max(c.z, c.w, gc,  xlo, xhi, ylo, yhi);

                bool rej = (mx0 < -1e-6f) || (mx1 < -1e-6f) || (mx2 < -1e-6f) ||
                           (imx <= 1e-8f);
                if (!rej) {
                    float mn0 = aff_min(a.x, a.y, a.z, xlo, xhi, ylo, yhi);
                    float mn1 = aff_min(a.w, c.x, c.y, xlo, xhi, ylo, yhi);
                    float mn2 = aff_min(U2,  V2,  W2,  xlo, xhi, ylo, yhi);
                    float imn = aff_min(c.z, c.w, gc,  xlo, xhi, ylo, yhi);
                    bool full = (mn0 > 1e-6f) && (mn1 > 1e-6f) && (mn2 > 1e-6f) &&
                                (imn > 1e-6f);
                    if (full) {
                        int s = atomicAdd(&nF, 1);
                        sfl[s] = make_float4(c.z, c.w, gc, 0.f);
                    } else {
                        int s = atomicAdd(&nP, 1);
                        spA[s] = a; spB[s] = c; spC[s] = gc;
                    }
                }
            }
        }
        __syncthreads();
        int np = nP, nf = nF;

        // partial: branchless per-pixel test (sign-bit OR, identical rounding
        // to reference for w0/w1/w2)
        for (int j = 0; j < np; j++) {
            float4 a = spA[j];
            float4 c = spB[j];
            float gc = spC[j];
            float ty0 = fmaf(a.y, y, a.z);
            float ty1 = fmaf(c.x, y, c.y);
            float tyi = fmaf(c.w, y, gc);
            {
                float w0 = fmaf(a.x, x0, ty0), w1 = fmaf(a.w, x0, ty1);
                float w2 = (1.0f - w0) - w1;
                float iv = fmaf(c.z, x0, tyi);
                unsigned s = __float_as_uint(w0) | __float_as_uint(w1) | __float_as_uint(w2);
                m0 = fmaxf(m0, __uint_as_float(__float_as_uint(iv) | (s & 0x80000000u)));
            }
            {
                float w0 = fmaf(a.x, x1, ty0), w1 = fmaf(a.w, x1, ty1);
                float w2 = (1.0f - w0) - w1;
                float iv = fmaf(c.z, x1, tyi);
                unsigned s = __float_as_uint(w0) | __float_as_uint(w1) | __float_as_uint(w2);
                m1 = fmaxf(m1, __uint_as_float(__float_as_uint(iv) | (s & 0x80000000u)));
            }
            {
                float w0 = fmaf(a.x, x2, ty0), w1 = fmaf(a.w, x2, ty1);
                float w2 = (1.0f - w0) - w1;
                float iv = fmaf(c.z, x2, tyi);
                unsigned s = __float_as_uint(w0) | __float_as_uint(w1) | __float_as_uint(w2);
                m2 = fmaxf(m2, __uint_as_float(__float_as_uint(iv) | (s & 0x80000000u)));
            }
            {
                float w0 = fmaf(a.x, x3, ty0), w1 = fmaf(a.w, x3, ty1);
                float w2 = (1.0f - w0) - w1;
                float iv = fmaf(c.z, x3, tyi);
                unsigned s = __float_as_uint(w0) | __float_as_uint(w1) | __float_as_uint(w2);
                m3 = fmaxf(m3, __uint_as_float(__float_as_uint(iv) | (s & 0x80000000u)));
            }
        }

        // full-accept: every pixel valid -> just interpolate inv and fmax
        #pragma unroll 2
        for (int j = 0; j < nf; j++) {
            float4 f = sfl[j];
            float tyi = fmaf(f.y, y, f.z);
            m0 = fmaxf(m0, fmaf(f.x, x0, tyi));
            m1 = fmaxf(m1, fmaf(f.x, x1, tyi));
            m2 = fmaxf(m2, fmaf(f.x, x2, tyi));
            m3 = fmaxf(m3, fmaf(f.x, x3, tyi));
        }
        __syncthreads();
    }

    unsigned* dst = g_inv + b * NPIX + iy * RW + ix0;
    if (m0 > 0.f) atomicMax(dst + 0, __float_as_uint(m0));
    if (m1 > 0.f) atomicMax(dst + 1, __float_as_uint(m1));
    if (m2 > 0.f) atomicMax(dst + 2, __float_as_uint(m2));
    if (m3 > 0.f) atomicMax(dst + 3, __float_as_uint(m3));
}

// ---------------- K3: inv -> z, mask, per-batch min/max ----------------------
__global__ void __launch_bounds__(256) k_zpass(float* __restrict__ dep,
                                               float* __restrict__ mask) {
    __shared__ float smx[256], smn[256];
    int idx = blockIdx.x * 256 + threadIdx.x;
    int b   = idx >> 16;
    int tid = threadIdx.x;

    float mi  = __uint_as_float(g_inv[idx]);
    bool  cov = mi > 0.f;
    float z   = cov ? fminf(FARV, 1.0f / mi) : FARV;

    dep [idx] = z;
    mask[idx] = cov ? 1.0f : 0.0f;

    smx[tid] = (cov && z < FARV) ? z : 0.0f;
    smn[tid] = z;
    __syncthreads();
    for (int s = 128; s > 0; s >>= 1) {
        if (tid < s) {
            smx[tid] = fmaxf(smx[tid], smx[tid + s]);
            smn[tid] = fminf(smn[tid], smn[tid + s]);
        }
        __syncthreads();
    }
    if (tid == 0) {
        atomicMax(&g_mx[b], __float_as_uint(smx[0]));
        atomicMin(&g_mn[b], __float_as_uint(smn[0]));
    }
}

// ---------------- K4: depth normalization ------------------------------------
__global__ void k_finalize(float* __restrict__ dep) {
    int idx = blockIdx.x * blockDim.x + threadIdx.x;
    if (idx >= B_ * NPIX) return;
    int b = idx >> 16;
    float mx = __uint_as_float(g_mx[b]);
    float mn = __uint_as_float(g_mn[b]);
    float z  = dep[idx];
    float nd = (mx - z) / (mx - mn + 1e-4f);
    dep[idx] = fminf(fmaxf(nd, 0.0f), 1.0f);
}

// ---------------- launch ------------------------------------------------------
extern "C" void kernel_launch(void* const* d_in, const int* in_sizes, int n_in,
                              void* d_out, int out_size) {
    const float* vertices = (const float*)d_in[0];
    const int*   faces    = (const int*)  d_in[1];
    const float* intr     = (const float*)d_in[2];
    const float* R        = (const float*)d_in[3];
    const float* t        = (const float*)d_in[4];
    const float* dist     = (const float*)d_in[5];

    float* out  = (float*)d_out;
    float* dep  = out;
    float* mask = out + B_ * NPIX;

    k_prep<<<B_ * NPIX / 256, 256>>>(vertices, faces, intr, R, t, dist);
    dim3 grid(RW / TILE, RW / TILE, B_ * S_);
    k_raster<<<grid, 256>>>();
    k_zpass<<<B_ * NPIX / 256, 256>>>(dep, mask);
    k_finalize<<<B_ * NPIX / 256, 256>>>(dep);
}

// round 4
// speedup vs baseline: 2.8387x; 1.1414x over previous
#include <cuda_runtime.h>
#include <cuda_bf16.h>
#include <cstdint>

#define B_   4
#define V_   778
#define F_   1538
#define NT   3076          // 2*F_ (faces + reversed)
#define RW   256
#define NPIX (RW * RW)
#define FARV 10.0f
#define TILE 32
#define TC   256
#define S_   16            // triangle slices per batch
#define SLICE ((NT + S_ - 1) / S_)   // 193  (single chunk per block)
#define HX   0.12109375f   // NDC half-extent of 31px tile span (31/256)

// ---------------- scratch (static device globals; no allocation) -------------
__device__ float4   g_e0  [B_ * NT];   // U0,V0,W0,E0
__device__ float4   g_e1  [B_ * NT];   // U1,V1,W1,E1
__device__ float4   g_e2  [B_ * NT];   // U2,V2,W2,E2
__device__ float4   g_gi  [B_ * NT];   // Gx,Gy,Gc,-
__device__ float4   g_bbox[B_ * NT];   // xmin,xmax,ymin,ymax
__device__ unsigned g_inv [B_ * NPIX]; // per-pixel max(inv) as ordered uint
__device__ unsigned g_mx  [B_];
__device__ unsigned g_mn  [B_];

// ---------------- projection helper ------------------------------------------
__device__ __forceinline__ float3 proj_vert(const float* __restrict__ verts,
                                            const float* __restrict__ Rb,
                                            const float* __restrict__ tb,
                                            const float* __restrict__ Kb,
                                            const float* __restrict__ db,
                                            int vglob) {
    const float* p = verts + vglob * 3;
    float px = p[0], py = p[1], pz = p[2];
    float x = Rb[0]*px + Rb[1]*py + Rb[2]*pz + tb[0];
    float y = Rb[3]*px + Rb[4]*py + Rb[5]*pz + tb[1];
    float z = Rb[6]*px + Rb[7]*py + Rb[8]*pz + tb[2];

    float zi = z + 1e-9f;
    float x_ = x / zi, y_ = y / zi;
    float k1 = db[0], k2 = db[1], p1 = db[2], p2 = db[3], k3 = db[4];
    float r2 = x_*x_ + y_*y_;
    float radial = 1.0f + k1*r2 + k2*r2*r2 + k3*r2*r2*r2;
    float x2 = x_*radial + 2.0f*p1*x_*y_ + p2*(r2 + 2.0f*x_*x_);
    float y2 = y_*radial + p1*(r2 + 2.0f*y_*y_) + 2.0f*p2*x_*y_;
    float u  = Kb[0]*x2 + Kb[1]*y2 + Kb[2];
    float vv = Kb[3]*x2 + Kb[4]*y2 + Kb[5];
    vv = 256.0f - vv;
    u  = 2.0f * (u  - 128.0f) / 256.0f;
    vv = 2.0f * (vv - 128.0f) / 256.0f;
    return make_float3(u, vv, z);
}

// ---------------- K1: fused setup (project inline) + scratch clear -----------
// grid: 256 blocks x 256 threads = 65536 threads (uint4 clear of g_inv)
__global__ void __launch_bounds__(256) k_prep(const float* __restrict__ verts,
                                              const int*   __restrict__ faces,
                                              const float* __restrict__ intr,
                                              const float* __restrict__ R,
                                              const float* __restrict__ t,
                                              const float* __restrict__ dist) {
    int gid = blockIdx.x * 256 + threadIdx.x;

    if (gid < B_ * NT) {
        int b  = gid / NT;
        int tt = gid - b * NT;
        const float* Rb = R    + b * 9;
        const float* tb = t    + b * 3;
        const float* Kb = intr + b * 9;
        const float* db = dist + b * 5;

        int base = (b * F_ + (tt < F_ ? tt : tt - F_)) * 3;
        int i0 = faces[base + 0], i1 = faces[base + 1], i2 = faces[base + 2];
        if (tt >= F_) { int tmp = i0; i0 = i2; i2 = tmp; }

        float3 A  = proj_vert(verts, Rb, tb, Kb, db, b * V_ + i0);
        float3 Bv = proj_vert(verts, Rb, tb, Kb, db, b * V_ + i1);
        float3 Cv = proj_vert(verts, Rb, tb, Kb, db, b * V_ + i2);
        float ax = A.x,  ay = A.y,  az = A.z;
        float bx = Bv.x, by = Bv.y, bz = Bv.z;
        float cx = Cv.x, cy = Cv.y, cz = Cv.z;

        float den = (bx - ax) * (cy - ay) - (by - ay) * (cx - ax);
        bool ok = (fabsf(den) > 1e-8f) && (az > 1e-8f) && (bz > 1e-8f) && (cz > 1e-8f);

        float4 e0, e1, e2, gi, bb;
        if (!ok) {
            e0 = make_float4(0.f, 0.f, -1e30f, 0.f);
            e1 = make_float4(0.f, 0.f, 0.f, 0.f);
            e2 = make_float4(0.f, 0.f, 0.f, 0.f);
            gi = make_float4(0.f, 0.f, 0.f, 0.f);
            bb = make_float4(2e30f, -2e30f, 2e30f, -2e30f);
        } else {
            float id = 1.0f / den;
            float U0 = (by - cy) * id, V0 = (cx - bx) * id;
            float W0 = -(U0 * cx + V0 * cy);
            float U1 = (cy - ay) * id, V1 = (ax - cx) * id;
            float W1 = -(U1 * cx + V1 * cy);
            float U2 = -(U0 + U1), V2 = -(V0 + V1), W2 = 1.0f - W0 - W1;
            float ra = 1.0f / az, rb = 1.0f / bz, rc = 1.0f / cz;
            float dA = ra - rc, dB = rb - rc;
            float Gx = U0 * dA + U1 * dB;
            float Gy = V0 * dA + V1 * dB;
            float Gc = rc + W0 * dA + W1 * dB;
            e0 = make_float4(U0, V0, W0, (fabsf(U0) + fabsf(V0)) * HX);
            e1 = make_float4(U1, V1, W1, (fabsf(U1) + fabsf(V1)) * HX);
            e2 = make_float4(U2, V2, W2, (fabsf(U2) + fabsf(V2)) * HX);
            gi = make_float4(Gx, Gy, Gc, 0.f);
            bb = make_float4(fminf(ax, fminf(bx, cx)), fmaxf(ax, fmaxf(bx, cx)),
                             fminf(ay, fminf(by, cy)), fmaxf(ay, fmaxf(by, cy)));
        }
        g_e0[gid] = e0; g_e1[gid] = e1; g_e2[gid] = e2;
        g_gi[gid] = gi; g_bbox[gid] = bb;
    }

    // vectorized clear of g_inv (65536 uint4 = 1MB)
    reinterpret_cast<uint4*>(g_inv)[gid] = make_uint4(0u, 0u, 0u, 0u);
    if (gid < B_) { g_mx[gid] = 0u; g_mn[gid] = __float_as_uint(FARV); }
}

// ---------------- K2: classified tiled rasterizer ----------------------------
// tile 32x32 px, 256 threads, 4 px/thread, 16 triangle slices; single chunk
__global__ void __launch_bounds__(256) k_raster() {
    __shared__ float4 spA[TC], spB[TC];
    __shared__ float  spC[TC];
    __shared__ float4 sfl[TC];
    __shared__ int    nP, nF;

    int bz = blockIdx.z;
    int b  = bz & (B_ - 1);
    int sl = bz >> 2;
    int t0 = sl * SLICE;
    int t1 = min(NT, t0 + SLICE);

    int tid = threadIdx.x;
    int row = tid >> 3;
    int xg  = tid & 7;
    int tx  = blockIdx.x * TILE;
    int ty  = blockIdx.y * TILE;
    int ix0 = tx + xg * 4;
    int iy  = ty + row;

    float y  = 2.0f * (iy + 0.5f) / 256.0f - 1.0f;
    float x0 = 2.0f * (ix0 + 0.5f) / 256.0f - 1.0f;
    float x1 = 2.0f * (ix0 + 1.5f) / 256.0f - 1.0f;
    float x2 = 2.0f * (ix0 + 2.5f) / 256.0f - 1.0f;
    float x3 = 2.0f * (ix0 + 3.5f) / 256.0f - 1.0f;

    // tile bounds + center
    float xlo = 2.0f * (tx +  0.5f) / 256.0f - 1.0f;
    float xhi = 2.0f * (tx + 31.5f) / 256.0f - 1.0f;
    float ylo = 2.0f * (ty +  0.5f) / 256.0f - 1.0f;
    float yhi = 2.0f * (ty + 31.5f) / 256.0f - 1.0f;
    float xc  = 0.5f * (xlo + xhi);
    float yc  = 0.5f * (ylo + yhi);

    const float4* e0p  = g_e0   + b * NT;
    const float4* e1p  = g_e1   + b * NT;
    const float4* e2p  = g_e2   + b * NT;
    const float4* gip  = g_gi   + b * NT;
    const float4* bbox = g_bbox + b * NT;

    if (tid == 0) { nP = 0; nF = 0; }
    __syncthreads();

    int tI = t0 + tid;
    if (tI < t1) {
        float4 bb = bbox[tI];
        if (bb.x <= xhi && bb.y >= xlo && bb.z <= yhi && bb.w >= ylo) {
            float4 r0 = e0p[tI];
            float4 r1 = e1p[tI];
            float4 r2 = e2p[tI];
            float cv0 = fmaf(r0.x, xc, fmaf(r0.y, yc, r0.z));
            float cv1 = fmaf(r1.x, xc, fmaf(r1.y, yc, r1.z));
            float cv2 = fmaf(r2.x, xc, fmaf(r2.y, yc, r2.z));
            float me0 = fmaf(r0.w, 2e-6f, 1e-6f);
            float me1 = fmaf(r1.w, 2e-6f, 1e-6f);
            float me2 = fmaf(r2.w, 2e-6f, 1e-6f);

            bool rej = (cv0 + r0.w < -me0) || (cv1 + r1.w < -me1) ||
                       (cv2 + r2.w < -me2);
            if (!rej) {
                float4 gi = gip[tI];
                bool full = (cv0 - r0.w > me0) && (cv1 - r1.w > me1) &&
                            (cv2 - r2.w > me2);
                if (full) {
                    int s = atomicAdd(&nF, 1);
                    sfl[s] = gi;
                } else {
                    int s = atomicAdd(&nP, 1);
                    spA[s] = make_float4(r0.x, r0.y, r0.z, r1.x);
                    spB[s] = make_float4(r1.y, r1.z, gi.x, gi.y);
                    spC[s] = gi.z;
                }
            }
        }
    }
    __syncthreads();
    int np = nP, nf = nF;

    float m0 = 0.f, m1 = 0.f, m2 = 0.f, m3 = 0.f;

    // partial: branchless per-pixel test (identical rounding to reference)
    for (int j = 0; j < np; j++) {
        float4 a = spA[j];
        float4 c = spB[j];
        float gc = spC[j];
        float ty0 = fmaf(a.y, y, a.z);
        float ty1 = fmaf(c.x, y, c.y);
        float tyi = fmaf(c.w, y, gc);
        {
            float w0 = fmaf(a.x, x0, ty0), w1 = fmaf(a.w, x0, ty1);
            float w2 = (1.0f - w0) - w1;
            float iv = fmaf(c.z, x0, tyi);
            unsigned s = __float_as_uint(w0) | __float_as_uint(w1) | __float_as_uint(w2);
            m0 = fmaxf(m0, __uint_as_float(__float_as_uint(iv) | (s & 0x80000000u)));
        }
        {
            float w0 = fmaf(a.x, x1, ty0), w1 = fmaf(a.w, x1, ty1);
            float w2 = (1.0f - w0) - w1;
            float iv = fmaf(c.z, x1, tyi);
            unsigned s = __float_as_uint(w0) | __float_as_uint(w1) | __float_as_uint(w2);
            m1 = fmaxf(m1, __uint_as_float(__float_as_uint(iv) | (s & 0x80000000u)));
        }
        {
            float w0 = fmaf(a.x, x2, ty0), w1 = fmaf(a.w, x2, ty1);
            float w2 = (1.0f - w0) - w1;
            float iv = fmaf(c.z, x2, tyi);
            unsigned s = __float_as_uint(w0) | __float_as_uint(w1) | __float_as_uint(w2);
            m2 = fmaxf(m2, __uint_as_float(__float_as_uint(iv) | (s & 0x80000000u)));
        }
        {
            float w0 = fmaf(a.x, x3, ty0), w1 = fmaf(a.w, x3, ty1);
            float w2 = (1.0f - w0) - w1;
            float iv = fmaf(c.z, x3, tyi);
            unsigned s = __float_as_uint(w0) | __float_as_uint(w1) | __float_as_uint(w2);
            m3 = fmaxf(m3, __uint_as_float(__float_as_uint(iv) | (s & 0x80000000u)));
        }
    }

    // full-accept: every pixel valid -> just interpolate inv and fmax
    #pragma unroll 2
    for (int j = 0; j < nf; j++) {
        float4 f = sfl[j];
        float tyi = fmaf(f.y, y, f.z);
        m0 = fmaxf(m0, fmaf(f.x, x0, tyi));
        m1 = fmaxf(m1, fmaf(f.x, x1, tyi));
        m2 = fmaxf(m2, fmaf(f.x, x2, tyi));
        m3 = fmaxf(m3, fmaf(f.x, x3, tyi));
    }

    unsigned* dst = g_inv + b * NPIX + iy * RW + ix0;
    if (m0 > 0.f) atomicMax(dst + 0, __float_as_uint(m0));
    if (m1 > 0.f) atomicMax(dst + 1, __float_as_uint(m1));
    if (m2 > 0.f) atomicMax(dst + 2, __float_as_uint(m2));
    if (m3 > 0.f) atomicMax(dst + 3, __float_as_uint(m3));
}

// ---------------- K3: inv -> z, mask, per-batch min/max (float4) -------------
// 256 blocks x 256 threads, 4 px/thread; each block within a single batch
__global__ void __launch_bounds__(256) k_zpass(float* __restrict__ dep,
                                               float* __restrict__ mask) {
    __shared__ float smx[256], smn[256];
    int idx4 = blockIdx.x * 256 + threadIdx.x;      // 0..65535
    int b    = idx4 >> 14;
    int tid  = threadIdx.x;

    uint4 mi = reinterpret_cast<const uint4*>(g_inv)[idx4];
    float z0 = mi.x ? fminf(FARV, 1.0f / __uint_as_float(mi.x)) : FARV;
    float z1 = mi.y ? fminf(FARV, 1.0f / __uint_as_float(mi.y)) : FARV;
    float z2 = mi.z ? fminf(FARV, 1.0f / __uint_as_float(mi.z)) : FARV;
    float z3 = mi.w ? fminf(FARV, 1.0f / __uint_as_float(mi.w)) : FARV;

    reinterpret_cast<float4*>(dep)[idx4]  = make_float4(z0, z1, z2, z3);
    reinterpret_cast<float4*>(mask)[idx4] = make_float4(mi.x ? 1.f : 0.f,
                                                        mi.y ? 1.f : 0.f,
                                                        mi.z ? 1.f : 0.f,
                                                        mi.w ? 1.f : 0.f);
    float fx0 = (mi.x && z0 < FARV) ? z0 : 0.f;
    float fx1 = (mi.y && z1 < FARV) ? z1 : 0.f;
    float fx2 = (mi.z && z2 < FARV) ? z2 : 0.f;
    float fx3 = (mi.w && z3 < FARV) ? z3 : 0.f;

    smx[tid] = fmaxf(fmaxf(fx0, fx1), fmaxf(fx2, fx3));
    smn[tid] = fminf(fminf(z0, z1), fminf(z2, z3));
    __syncthreads();
    for (int s = 128; s > 0; s >>= 1) {
        if (tid < s) {
            smx[tid] = fmaxf(smx[tid], smx[tid + s]);
            smn[tid] = fminf(smn[tid], smn[tid + s]);
        }
        __syncthreads();
    }
    if (tid == 0) {
        atomicMax(&g_mx[b], __float_as_uint(smx[0]));
        atomicMin(&g_mn[b], __float_as_uint(smn[0]));
    }
}

// ---------------- K4: depth normalization (float4) ---------------------------
__global__ void __launch_bounds__(256) k_finalize(float* __restrict__ dep) {
    int idx4 = blockIdx.x * 256 + threadIdx.x;
    int b    = idx4 >> 14;
    float mx = __uint_as_float(g_mx[b]);
    float rd = 1.0f / (mx - __uint_as_float(g_mn[b]) + 1e-4f);
    float4 z = reinterpret_cast<const float4*>(dep)[idx4];
    float4 o;
    o.x = fminf(fmaxf((mx - z.x) * rd, 0.0f), 1.0f);
    o.y = fminf(fmaxf((mx - z.y) * rd, 0.0f), 1.0f);
    o.z = fminf(fmaxf((mx - z.z) * rd, 0.0f), 1.0f);
    o.w = fminf(fmaxf((mx - z.w) * rd, 0.0f), 1.0f);
    reinterpret_cast<float4*>(dep)[idx4] = o;
}

// ---------------- launch ------------------------------------------------------
extern "C" void kernel_launch(void* const* d_in, const int* in_sizes, int n_in,
                              void* d_out, int out_size) {
    const float* vertices = (const float*)d_in[0];
    const int*   faces    = (const int*)  d_in[1];
    const float* intr     = (const float*)d_in[2];
    const float* R        = (const float*)d_in[3];
    const float* t        = (const float*)d_in[4];
    const float* dist     = (const float*)d_in[5];

    float* out  = (float*)d_out;
    float* dep  = out;
    float* mask = out + B_ * NPIX;

    k_prep<<<256, 256>>>(vertices, faces, intr, R, t, dist);
    dim3 grid(RW / TILE, RW / TILE, B_ * S_);
    k_raster<<<grid, 256>>>();
    k_zpass<<<256, 256>>>(dep, mask);
    k_finalize<<<256, 256>>>(dep);
}